// round 14
// baseline (speedup 1.0000x reference)
#include <cuda_runtime.h>
#include <cuda_bf16.h>
#include <cuda_fp16.h>
#include <cstdint>
#include <math.h>

#define Bb   2
#define Tt   2048
#define HIDD 2048
#define NH   16
#define KVH  4
#define HD   128
#define Mrows (Bb*Tt)

// ---------------- scratch (device globals: allocation-free) ----------------
__device__ float g_Q[(size_t)Bb*NH*Tt*HD];    // [B, NH, T, HD]
__device__ float g_K[(size_t)Bb*KVH*Tt*HD];   // [B, KVH, T, HD]
__device__ float g_V[(size_t)Bb*KVH*Tt*HD];   // [B, KVH, T, HD]
__device__ float g_ctx[(size_t)Bb*Tt*HIDD];   // [B*T, HID]

// ================= mma.sync helpers (compute_103-safe) =====================
__device__ __forceinline__ uint32_t smem_u32(const void* p) {
    uint32_t a;
    asm("{ .reg .u64 t; cvta.to.shared.u64 t, %1; cvt.u32.u64 %0, t; }" : "=r"(a) : "l"(p));
    return a;
}
__device__ __forceinline__ void ldm_x4(uint32_t& r0, uint32_t& r1, uint32_t& r2,
                                       uint32_t& r3, uint32_t addr) {
    asm volatile("ldmatrix.sync.aligned.m8n8.x4.shared.b16 {%0,%1,%2,%3}, [%4];"
                 : "=r"(r0), "=r"(r1), "=r"(r2), "=r"(r3) : "r"(addr));
}
__device__ __forceinline__ void ldm_x4_trans(uint32_t& r0, uint32_t& r1, uint32_t& r2,
                                             uint32_t& r3, uint32_t addr) {
    asm volatile("ldmatrix.sync.aligned.m8n8.x4.trans.shared.b16 {%0,%1,%2,%3}, [%4];"
                 : "=r"(r0), "=r"(r1), "=r"(r2), "=r"(r3) : "r"(addr));
}
// fp16 mma
__device__ __forceinline__ void mma16816h(float* c, uint32_t a0, uint32_t a1,
                                          uint32_t a2, uint32_t a3,
                                          uint32_t b0, uint32_t b1) {
    asm volatile(
        "mma.sync.aligned.m16n8k16.row.col.f32.f16.f16.f32 "
        "{%0,%1,%2,%3}, {%4,%5,%6,%7}, {%8,%9}, {%0,%1,%2,%3};"
        : "+f"(c[0]), "+f"(c[1]), "+f"(c[2]), "+f"(c[3])
        : "r"(a0), "r"(a1), "r"(a2), "r"(a3), "r"(b0), "r"(b1));
}
__device__ __forceinline__ float ex2(float x) {
    float r;
    asm("ex2.approx.f32 %0, %1;" : "=f"(r) : "f"(x));
    return r;
}

// ---- fp16 split helpers ----
__device__ __forceinline__ void split4h(float4 v, uint32_t& h0, uint32_t& h1,
                                        uint32_t& l0, uint32_t& l1) {
    __half2 a = __floats2half2_rn(v.x, v.y);
    __half2 b = __floats2half2_rn(v.z, v.w);
    __half2 ra = __floats2half2_rn(v.x - __half2float(a.x),
                                   v.y - __half2float(a.y));
    __half2 rb = __floats2half2_rn(v.z - __half2float(b.x),
                                   v.w - __half2float(b.y));
    h0 = *(uint32_t*)&a; h1 = *(uint32_t*)&b;
    l0 = *(uint32_t*)&ra; l1 = *(uint32_t*)&rb;
}
__device__ __forceinline__ void round4h(float4 v, uint32_t& h0, uint32_t& h1) {
    __half2 a = __floats2half2_rn(v.x, v.y);
    __half2 b = __floats2half2_rn(v.z, v.w);
    h0 = *(uint32_t*)&a; h1 = *(uint32_t*)&b;
}
__device__ __forceinline__ uint32_t pack_h(float x, float y) {
    __half2 h = __floats2half2_rn(x, y);
    return *(uint32_t*)&h;
}

// ======== fp16 2-term GEMM body: C[M,N] = A[M,K] @ W[K,N] ==================
// 128x128 tile, BK=64, 256 threads, 2 CTAs/SM, dynamic smem (54.25 KB/CTA).
// A split exactly into fp16 hi/lo; W rounded once to fp16.
#define SP  72      // A smem row stride in fp16 (64 data + 8 pad) -> 144B rows
#define BSP 136     // B smem row stride in fp16 (128 data + 8 pad) -> 272B rows
#define GA_H 0
#define GA_L 18432
#define GB_H 36864
#define G_SMEM 54272

__device__ __forceinline__ void gemm_body(
    const float* __restrict__ A, const float* __restrict__ W,
    float* __restrict__ C, int N, int K, int mode, int H, int m0, int n0)
{
    extern __shared__ char gsm[];
    uint16_t* sAh = (uint16_t*)(gsm + GA_H);
    uint16_t* sAl = (uint16_t*)(gsm + GA_L);
    uint16_t* sBh = (uint16_t*)(gsm + GB_H);
    const uint32_t uAh = smem_u32(sAh), uAl = smem_u32(sAl);
    const uint32_t uBh = smem_u32(sBh);

    int tid = threadIdx.x;
    int wid = tid >> 5, lane = tid & 31;
    int wm = wid >> 2, wn = wid & 3;

    int arow = tid >> 1;                 // 0..127
    int acb  = (tid & 1) << 5;           // 0 or 32 (cols, fp32)
    int bk0  = tid >> 5;                 // 0..7 (k row base)
    int bn4  = (tid & 31) << 2;          // 0..124 (n group of 4)

    const float* apg = A + (size_t)(m0 + arow) * K + acb;
    const float* bpg = W + (size_t)bk0 * N + n0 + bn4;

    float acc[4][4][4];
    #pragma unroll
    for (int i = 0; i < 4; ++i)
        #pragma unroll
        for (int j = 0; j < 4; ++j)
            #pragma unroll
            for (int e = 0; e < 4; ++e) acc[i][j][e] = 0.f;

    for (int k0 = 0; k0 < K; k0 += 64) {
        // ---- stage A: [128 m][64 k] fp32 -> fp16 hi/lo ----
        #pragma unroll
        for (int c = 0; c < 8; ++c) {
            float4 v = *(const float4*)(apg + k0 + (c << 2));
            uint32_t h0, h1, l0, l1;
            split4h(v, h0, h1, l0, l1);
            uint32_t off = (uint32_t)(arow * SP + acb + (c << 2)) << 1;
            *(uint32_t*)((char*)sAh + off)     = h0;
            *(uint32_t*)((char*)sAh + off + 4) = h1;
            *(uint32_t*)((char*)sAl + off)     = l0;
            *(uint32_t*)((char*)sAl + off + 4) = l1;
        }
        // ---- stage B: [64 k][128 n] fp32 -> fp16 (rounded once) ----
        #pragma unroll
        for (int it = 0; it < 8; ++it) {
            float4 v = *(const float4*)(bpg + (size_t)(k0 + bk0 + (it << 3) - bk0 + (it << 3) == 0 ? (k0 + (it << 3)) : (k0 + (it << 3))) * N);
            // (simplified below)
            (void)v;
            break;
        }
        #pragma unroll
        for (int it = 0; it < 8; ++it) {
            float4 v = *(const float4*)(bpg + (size_t)(k0 + (it << 3)) * N);
            uint32_t h0, h1;
            round4h(v, h0, h1);
            uint32_t off = (uint32_t)((bk0 + (it << 3)) * BSP + bn4) << 1;
            *(uint32_t*)((char*)sBh + off)     = h0;
            *(uint32_t*)((char*)sBh + off + 4) = h1;
        }
        __syncthreads();

        int r16 = lane & 15, hsel = lane >> 4;
        #pragma unroll
        for (int ks = 0; ks < 4; ++ks) {
            uint32_t bh[2][4];
            #pragma unroll
            for (int j2 = 0; j2 < 2; ++j2) {
                uint32_t boff = (uint32_t)((ks * 16 + r16) * BSP +
                                           (wn << 5) + (j2 << 4) + (hsel << 3)) << 1;
                ldm_x4_trans(bh[j2][0], bh[j2][1], bh[j2][2], bh[j2][3], uBh + boff);
            }
            #pragma unroll
            for (int ii = 0; ii < 4; ++ii) {
                uint32_t aoff = (uint32_t)(((wm << 6) + (ii << 4) + r16) * SP +
                                           ks * 16 + (hsel << 3)) << 1;
                uint32_t ah0, ah1, ah2, ah3, al0, al1, al2, al3;
                ldm_x4(ah0, ah1, ah2, ah3, uAh + aoff);
                ldm_x4(al0, al1, al2, al3, uAl + aoff);
                #pragma unroll
                for (int j2 = 0; j2 < 2; ++j2) {
                    mma16816h(acc[ii][2*j2],   ah0, ah1, ah2, ah3, bh[j2][0], bh[j2][1]);
                    mma16816h(acc[ii][2*j2+1], ah0, ah1, ah2, ah3, bh[j2][2], bh[j2][3]);
                    mma16816h(acc[ii][2*j2],   al0, al1, al2, al3, bh[j2][0], bh[j2][1]);
                    mma16816h(acc[ii][2*j2+1], al0, al1, al2, al3, bh[j2][2], bh[j2][3]);
                }
            }
        }
        __syncthreads();
    }

    int g = lane >> 2, q = lane & 3;
    #pragma unroll
    for (int i = 0; i < 4; ++i) {
        #pragma unroll
        for (int half = 0; half < 2; ++half) {
            int m = m0 + (wm << 6) + (i << 4) + g + (half << 3);
            float* dst;
            if (mode == 0) {
                dst = C + (size_t)m * N + n0;
            } else {
                int b = m >> 11, t = m & (Tt - 1), h = n0 >> 7;
                dst = C + (((size_t)(b * H + h) * Tt + t) << 7);
            }
            #pragma unroll
            for (int j = 0; j < 4; ++j) {
                int nl = (wn << 5) + (j << 3) + (q << 1);
                float2 v;
                v.x = acc[i][j][half * 2];
                v.y = acc[i][j][half * 2 + 1];
                *(float2*)(dst + nl) = v;
            }
        }
    }
}

// ---- fused QKV projection: one launch, W selected by blockIdx.x ----
__global__ __launch_bounds__(256, 2) void qkv_gemm_kernel(
    const float* __restrict__ A,
    const float* __restrict__ Wq, const float* __restrict__ Wk,
    const float* __restrict__ Wv,
    float* __restrict__ Qo, float* __restrict__ Ko, float* __restrict__ Vo)
{
    int x = blockIdx.x;
    int m0 = blockIdx.y << 7;
    const float* W; float* C; int N, H, n0;
    if (x < 16)      { W = Wq; C = Qo; N = NH*HD;  H = NH;  n0 = x << 7; }
    else if (x < 20) { W = Wk; C = Ko; N = KVH*HD; H = KVH; n0 = (x - 16) << 7; }
    else             { W = Wv; C = Vo; N = KVH*HD; H = KVH; n0 = (x - 20) << 7; }
    gemm_body(A, W, C, N, HIDD, 1, H, m0, n0);
}

// ---- generic GEMM (output projection) ----
__global__ __launch_bounds__(256, 2) void tc_gemm_kernel(
    const float* __restrict__ A, const float* __restrict__ W,
    float* __restrict__ C, int N, int K, int mode, int H)
{
    gemm_body(A, W, C, N, K, mode, H, blockIdx.y << 7, blockIdx.x << 7);
}

// ---------------- RoPE (in-place on [B,H,T,HD]) ----------------
__global__ void rope_kernel(float* __restrict__ X, const float* __restrict__ cs,
                            const float* __restrict__ sn, int total)
{
    int i = blockIdx.x * blockDim.x + threadIdx.x;
    if (i >= total) return;
    int d = i & 63;
    int rest = i >> 6;
    int t = rest & (Tt - 1);
    float* row = X + ((size_t)rest << 7);
    float x1 = row[d], x2 = row[d + 64];
    float c1 = cs[(t << 7) + d],      s1 = sn[(t << 7) + d];
    float c2 = cs[(t << 7) + d + 64], s2 = sn[(t << 7) + d + 64];
    row[d]      = x1 * c1 - x2 * s1;
    row[d + 64] = x2 * c2 + x1 * s2;
}

// ========== Flash attention (fp16: 2-term S, 1-term PV; causal, GQA) =======
#define FSP 136

__global__ __launch_bounds__(256, 1) void flash_mma_kernel(
    const float* __restrict__ Q, const float* __restrict__ K,
    const float* __restrict__ V, float* __restrict__ ctx)
{
    extern __shared__ char fsm[];
    uint16_t* Qh = (uint16_t*)fsm;
    uint16_t* Ql = Qh + 128 * FSP;
    uint16_t* Kh = Ql + 128 * FSP;
    uint16_t* Vh = Kh + 64 * FSP;
    const uint32_t uQh = smem_u32(Qh), uQl = smem_u32(Ql);
    const uint32_t uKh = smem_u32(Kh), uVh = smem_u32(Vh);

    int tid = threadIdx.x, wid = tid >> 5, lane = tid & 31;
    int g = lane >> 2, qd = lane & 3;
    int r16 = lane & 15, hsel = lane >> 4;
    int qt = gridDim.x - 1 - blockIdx.x;
    int bh = blockIdx.y;
    int b = bh >> 4, h = bh & 15, kvh = h >> 2;

    const float* Qp = Q + (((size_t)(b * NH + h) * Tt + qt * 128) << 7);
    const float* Kp = K + (((size_t)(b * KVH + kvh) * Tt) << 7);
    const float* Vp = V + (((size_t)(b * KVH + kvh) * Tt) << 7);

    {
        int row = tid >> 1, cb = (tid & 1) << 6;
        const float* qp = Qp + ((size_t)row << 7) + cb;
        #pragma unroll
        for (int i = 0; i < 16; ++i) {
            float4 v = *(const float4*)(qp + (i << 2));
            uint32_t h0, h1, l0, l1;
            split4h(v, h0, h1, l0, l1);
            uint32_t off = (uint32_t)(row * FSP + cb + (i << 2)) << 1;
            *(uint32_t*)((char*)Qh + off)     = h0;
            *(uint32_t*)((char*)Qh + off + 4) = h1;
            *(uint32_t*)((char*)Ql + off)     = l0;
            *(uint32_t*)((char*)Ql + off + 4) = l1;
        }
    }

    float o[16][4];
    #pragma unroll
    for (int i = 0; i < 16; ++i)
        #pragma unroll
        for (int e = 0; e < 4; ++e) o[i][e] = 0.f;
    float m0 = -1e30f, m1 = -1e30f, l0 = 0.f, l1 = 0.f;
    const float alpha = 0.08838834764831845f * 1.4426950408889634f;

    int qbase = qt * 128 + wid * 16;
    int ntiles = 2 * qt + 2;

    int srow = tid >> 2, scb = (tid & 3) << 5;

    float4 kr[8], vr[8];
    {
        const float* kp = Kp + ((size_t)srow << 7) + scb;
        const float* vp = Vp + ((size_t)srow << 7) + scb;
        #pragma unroll
        for (int i = 0; i < 8; ++i) {
            kr[i] = *(const float4*)(kp + (i << 2));
            vr[i] = *(const float4*)(vp + (i << 2));
        }
    }

    for (int jt = 0; jt < ntiles; ++jt) {
        __syncthreads();
        #pragma unroll
        for (int i = 0; i < 8; ++i) {
            uint32_t off = (uint32_t)(srow * FSP + scb + (i << 2)) << 1;
            uint32_t h0, h1;
            round4h(kr[i], h0, h1);
            *(uint32_t*)((char*)Kh + off)     = h0;
            *(uint32_t*)((char*)Kh + off + 4) = h1;
            round4h(vr[i], h0, h1);
            *(uint32_t*)((char*)Vh + off)     = h0;
            *(uint32_t*)((char*)Vh + off + 4) = h1;
        }
        __syncthreads();

        if (jt + 1 < ntiles) {
            const float* kp = Kp + ((size_t)((jt + 1) * 64 + srow) << 7) + scb;
            const float* vp = Vp + ((size_t)((jt + 1) * 64 + srow) << 7) + scb;
            #pragma unroll
            for (int i = 0; i < 8; ++i) {
                kr[i] = *(const float4*)(kp + (i << 2));
                vr[i] = *(const float4*)(vp + (i << 2));
            }
        }

        float s[8][4];
        #pragma unroll
        for (int t8 = 0; t8 < 8; ++t8)
            #pragma unroll
            for (int e = 0; e < 4; ++e) s[t8][e] = 0.f;

        #pragma unroll
        for (int ks = 0; ks < 8; ++ks) {
            uint32_t aoff = (uint32_t)((wid * 16 + r16) * FSP + ks * 16 + (hsel << 3)) << 1;
            uint32_t ah0, ah1, ah2, ah3, al0, al1, al2, al3;
            ldm_x4(ah0, ah1, ah2, ah3, uQh + aoff);
            ldm_x4(al0, al1, al2, al3, uQl + aoff);
            #pragma unroll
            for (int nt = 0; nt < 4; ++nt) {
                uint32_t koff = (uint32_t)((nt * 16 + r16) * FSP + ks * 16 + (hsel << 3)) << 1;
                uint32_t kh0, kh1, kh2, kh3;
                ldm_x4(kh0, kh1, kh2, kh3, uKh + koff);
                mma16816h(s[2*nt],   ah0, ah1, ah2, ah3, kh0, kh2);
                mma16816h(s[2*nt+1], ah0, ah1, ah2, ah3, kh1, kh3);
                mma16816h(s[2*nt],   al0, al1, al2, al3, kh0, kh2);
                mma16816h(s[2*nt+1], al0, al1, al2, al3, kh1, kh3);
            }
        }

        int kvb = jt * 64;
        int qr0 = qbase + g;
        bool needmask = (kvb + 63 > qbase);
        #pragma unroll
        for (int t8 = 0; t8 < 8; ++t8) {
            #pragma unroll
            for (int e = 0; e < 4; ++e) {
                float val = s[t8][e] * alpha;
                if (needmask) {
                    int col = kvb + t8 * 8 + qd * 2 + (e & 1);
                    int row = (e < 2) ? qr0 : qr0 + 8;
                    if (col > row) val = -1e30f;
                }
                s[t8][e] = val;
            }
        }

        float tm0 = -1e30f, tm1 = -1e30f;
        #pragma unroll
        for (int t8 = 0; t8 < 8; ++t8) {
            tm0 = fmaxf(tm0, fmaxf(s[t8][0], s[t8][1]));
            tm1 = fmaxf(tm1, fmaxf(s[t8][2], s[t8][3]));
        }
        tm0 = fmaxf(tm0, __shfl_xor_sync(0xffffffffu, tm0, 1));
        tm0 = fmaxf(tm0, __shfl_xor_sync(0xffffffffu, tm0, 2));
        tm1 = fmaxf(tm1, __shfl_xor_sync(0xffffffffu, tm1, 1));
        tm1 = fmaxf(tm1, __shfl_xor_sync(0xffffffffu, tm1, 2));
        float nm0 = fmaxf(m0, tm0), nm1 = fmaxf(m1, tm1);
        float c0 = ex2(m0 - nm0), c1 = ex2(m1 - nm1);
        m0 = nm0; m1 = nm1;

        float ps0 = 0.f, ps1 = 0.f;
        #pragma unroll
        for (int t8 = 0; t8 < 8; ++t8) {
            s[t8][0] = ex2(s[t8][0] - nm0);
            s[t8][1] = ex2(s[t8][1] - nm0);
            s[t8][2] = ex2(s[t8][2] - nm1);
            s[t8][3] = ex2(s[t8][3] - nm1);
            ps0 += s[t8][0] + s[t8][1];
            ps1 += s[t8][2] + s[t8][3];
        }
        ps0 += __shfl_xor_sync(0xffffffffu, ps0, 1);
        ps0 += __shfl_xor_sync(0xffffffffu, ps0, 2);
        ps1 += __shfl_xor_sync(0xffffffffu, ps1, 1);
        ps1 += __shfl_xor_sync(0xffffffffu, ps1, 2);
        l0 = l0 * c0 + ps0;
        l1 = l1 * c1 + ps1;

        #pragma unroll
        for (int dt = 0; dt < 16; ++dt) {
            o[dt][0] *= c0; o[dt][1] *= c0;
            o[dt][2] *= c1; o[dt][3] *= c1;
        }

        #pragma unroll
        for (int j = 0; j < 4; ++j) {
            uint32_t ph0 = pack_h(s[2*j][0],   s[2*j][1]);
            uint32_t ph1 = pack_h(s[2*j][2],   s[2*j][3]);
            uint32_t ph2 = pack_h(s[2*j+1][0], s[2*j+1][1]);
            uint32_t ph3 = pack_h(s[2*j+1][2], s[2*j+1][3]);
            #pragma unroll
            for (int dt = 0; dt < 8; ++dt) {
                uint32_t voff = (uint32_t)((j * 16 + r16) * FSP + dt * 16 + (hsel << 3)) << 1;
                uint32_t vh0, vh1, vh2, vh3;
                ldm_x4_trans(vh0, vh1, vh2, vh3, uVh + voff);
                mma16816h(o[2*dt],   ph0, ph1, ph2, ph3, vh0, vh1);
                mma16816h(o[2*dt+1], ph0, ph1, ph2, ph3, vh2, vh3);
            }
        }
    }

    float li0 = 1.f / l0, li1 = 1.f / l1;
    int t0 = qbase + g;
    float* dst0 = ctx + (size_t)(b * Tt + t0) * HIDD + h * HD;
    float* dst1 = ctx + (size_t)(b * Tt + t0 + 8) * HIDD + h * HD;
    #pragma unroll
    for (int dt = 0; dt < 16; ++dt) {
        int col = dt * 8 + qd * 2;
        float2 w0 = make_float2(o[dt][0] * li0, o[dt][1] * li0);
        float2 w1 = make_float2(o[dt][2] * li1, o[dt][3] * li1);
        *(float2*)(dst0 + col) = w0;
        *(float2*)(dst1 + col) = w1;
    }
}

// ---------------- launch ----------------
extern "C" void kernel_launch(void* const* d_in, const int* in_sizes, int n_in,
                              void* d_out, int out_size)
{
    const float* hs   = (const float*)d_in[0];
    const float* cosp = (const float*)d_in[2];
    const float* sinp = (const float*)d_in[3];
    const float* Wq   = (const float*)d_in[4];
    const float* Wk   = (const float*)d_in[5];
    const float* Wv   = (const float*)d_in[6];
    const float* Wo   = (const float*)d_in[7];
    float* out = (float*)d_out;

    float *pQ, *pK, *pV, *pC;
    cudaGetSymbolAddress((void**)&pQ, g_Q);
    cudaGetSymbolAddress((void**)&pK, g_K);
    cudaGetSymbolAddress((void**)&pV, g_V);
    cudaGetSymbolAddress((void**)&pC, g_ctx);

    cudaFuncSetAttribute(qkv_gemm_kernel, cudaFuncAttributeMaxDynamicSharedMemorySize, G_SMEM);
    cudaFuncSetAttribute(tc_gemm_kernel,  cudaFuncAttributeMaxDynamicSharedMemorySize, G_SMEM);

    // Fused QKV projection (fp16 2-term, BK=64, 2 CTAs/SM)
    qkv_gemm_kernel<<<dim3(24, 32), 256, G_SMEM>>>(hs, Wq, Wk, Wv, pQ, pK, pV);

    // RoPE on Q and K
    int totQ = Bb * NH  * Tt * 64;
    int totK = Bb * KVH * Tt * 64;
    rope_kernel<<<totQ / 256, 256>>>(pQ, cosp, sinp, totQ);
    rope_kernel<<<totK / 256, 256>>>(pK, cosp, sinp, totK);

    // Flash attention (fp16 2-term S, 1-term PV)
    size_t fsh = (size_t)(2 * 128 * FSP + 2 * 64 * FSP) * sizeof(uint16_t); // 104448
    cudaFuncSetAttribute(flash_mma_kernel, cudaFuncAttributeMaxDynamicSharedMemorySize, (int)fsh);
    flash_mma_kernel<<<dim3(Tt/128, Bb*NH), 256, fsh>>>(pQ, pK, pV, pC);

    // Output projection (fp16 2-term, BK=64) -> d_out
    tc_gemm_kernel<<<dim3(16, 32), 256, G_SMEM>>>(pC, Wo, out, HIDD, HIDD, 0, 0);
}

// round 15
// speedup vs baseline: 1.3759x; 1.3759x over previous
#include <cuda_runtime.h>
#include <cuda_bf16.h>
#include <cuda_fp16.h>
#include <cstdint>
#include <math.h>

#define Bb   2
#define Tt   2048
#define HIDD 2048
#define NH   16
#define KVH  4
#define HD   128
#define Mrows (Bb*Tt)

// ---------------- scratch (device globals: allocation-free) ----------------
__device__ float g_Q[(size_t)Bb*NH*Tt*HD];        // fp32 Q (pre-RoPE)
__device__ float g_K[(size_t)Bb*KVH*Tt*HD];       // fp32 K (pre-RoPE)
__device__ __half g_Qh[(size_t)Bb*NH*Tt*HD];      // fp16 Q hi (post-RoPE)
__device__ __half g_Ql[(size_t)Bb*NH*Tt*HD];      // fp16 Q lo
__device__ __half g_Kh[(size_t)Bb*KVH*Tt*HD];     // fp16 K (rounded, post-RoPE)
__device__ __half g_Vh[(size_t)Bb*KVH*Tt*HD];     // fp16 V (rounded)
__device__ float g_ctx[(size_t)Bb*Tt*HIDD];       // [B*T, HID]

// ================= mma.sync helpers (compute_103-safe) =====================
__device__ __forceinline__ uint32_t smem_u32(const void* p) {
    uint32_t a;
    asm("{ .reg .u64 t; cvta.to.shared.u64 t, %1; cvt.u32.u64 %0, t; }" : "=r"(a) : "l"(p));
    return a;
}
__device__ __forceinline__ void ldm_x4(uint32_t& r0, uint32_t& r1, uint32_t& r2,
                                       uint32_t& r3, uint32_t addr) {
    asm volatile("ldmatrix.sync.aligned.m8n8.x4.shared.b16 {%0,%1,%2,%3}, [%4];"
                 : "=r"(r0), "=r"(r1), "=r"(r2), "=r"(r3) : "r"(addr));
}
__device__ __forceinline__ void ldm_x4_trans(uint32_t& r0, uint32_t& r1, uint32_t& r2,
                                             uint32_t& r3, uint32_t addr) {
    asm volatile("ldmatrix.sync.aligned.m8n8.x4.trans.shared.b16 {%0,%1,%2,%3}, [%4];"
                 : "=r"(r0), "=r"(r1), "=r"(r2), "=r"(r3) : "r"(addr));
}
__device__ __forceinline__ void mma16816h(float* c, uint32_t a0, uint32_t a1,
                                          uint32_t a2, uint32_t a3,
                                          uint32_t b0, uint32_t b1) {
    asm volatile(
        "mma.sync.aligned.m16n8k16.row.col.f32.f16.f16.f32 "
        "{%0,%1,%2,%3}, {%4,%5,%6,%7}, {%8,%9}, {%0,%1,%2,%3};"
        : "+f"(c[0]), "+f"(c[1]), "+f"(c[2]), "+f"(c[3])
        : "r"(a0), "r"(a1), "r"(a2), "r"(a3), "r"(b0), "r"(b1));
}
__device__ __forceinline__ float ex2(float x) {
    float r;
    asm("ex2.approx.f32 %0, %1;" : "=f"(r) : "f"(x));
    return r;
}
__device__ __forceinline__ void cpa16(uint32_t dst, const void* src) {
    asm volatile("cp.async.cg.shared.global [%0], [%1], 16;" :: "r"(dst), "l"(src));
}
#define CPA_COMMIT() asm volatile("cp.async.commit_group;" ::: "memory")
#define CPA_WAIT1()  asm volatile("cp.async.wait_group 1;" ::: "memory")
#define CPA_WAIT0()  asm volatile("cp.async.wait_group 0;" ::: "memory")

// ---- fp16 split helpers ----
__device__ __forceinline__ void split4h(float4 v, uint32_t& h0, uint32_t& h1,
                                        uint32_t& l0, uint32_t& l1) {
    __half2 a = __floats2half2_rn(v.x, v.y);
    __half2 b = __floats2half2_rn(v.z, v.w);
    __half2 ra = __floats2half2_rn(v.x - __half2float(a.x),
                                   v.y - __half2float(a.y));
    __half2 rb = __floats2half2_rn(v.z - __half2float(b.x),
                                   v.w - __half2float(b.y));
    h0 = *(uint32_t*)&a; h1 = *(uint32_t*)&b;
    l0 = *(uint32_t*)&ra; l1 = *(uint32_t*)&rb;
}
__device__ __forceinline__ void round4h(float4 v, uint32_t& h0, uint32_t& h1) {
    __half2 a = __floats2half2_rn(v.x, v.y);
    __half2 b = __floats2half2_rn(v.z, v.w);
    h0 = *(uint32_t*)&a; h1 = *(uint32_t*)&b;
}
__device__ __forceinline__ uint32_t pack_h(float x, float y) {
    __half2 h = __floats2half2_rn(x, y);
    return *(uint32_t*)&h;
}

// ======== fp16 2-term GEMM (R11 config: BK=32, static smem, 2 CTA/SM) ======
// mode 0: fp32 row-major.  mode 1: fp32 head layout.  mode 3: fp16 head layout.
#define SP  40
#define BSP 136

__device__ __forceinline__ void gemm_body(
    const float* __restrict__ A, const float* __restrict__ W,
    float* __restrict__ C, __half* __restrict__ Ch,
    int N, int K, int mode, int H, int m0, int n0)
{
    __shared__ __align__(16) uint16_t sAh[128 * SP];
    __shared__ __align__(16) uint16_t sAl[128 * SP];
    __shared__ __align__(16) uint16_t sBh[32 * BSP];

    const uint32_t uAh = smem_u32(sAh), uAl = smem_u32(sAl);
    const uint32_t uBh = smem_u32(sBh);

    int tid = threadIdx.x;
    int wid = tid >> 5, lane = tid & 31;
    int wm = wid >> 2, wn = wid & 3;

    int arow = tid >> 1;
    int acb  = (tid & 1) << 4;
    int bk0  = tid >> 5;
    int bn4  = (tid & 31) << 2;

    const float* apg = A + (size_t)(m0 + arow) * K + acb;
    const float* bpg = W + (size_t)bk0 * N + n0 + bn4;

    float acc[4][4][4];
    #pragma unroll
    for (int i = 0; i < 4; ++i)
        #pragma unroll
        for (int j = 0; j < 4; ++j)
            #pragma unroll
            for (int e = 0; e < 4; ++e) acc[i][j][e] = 0.f;

    for (int k0 = 0; k0 < K; k0 += 32) {
        #pragma unroll
        for (int c = 0; c < 4; ++c) {
            float4 v = *(const float4*)(apg + k0 + (c << 2));
            uint32_t h0, h1, l0, l1;
            split4h(v, h0, h1, l0, l1);
            uint32_t off = (uint32_t)(arow * SP + acb + (c << 2)) << 1;
            *(uint32_t*)((char*)sAh + off)     = h0;
            *(uint32_t*)((char*)sAh + off + 4) = h1;
            *(uint32_t*)((char*)sAl + off)     = l0;
            *(uint32_t*)((char*)sAl + off + 4) = l1;
        }
        #pragma unroll
        for (int it = 0; it < 4; ++it) {
            float4 v = *(const float4*)(bpg + (size_t)(k0 + (it << 3)) * N);
            uint32_t h0, h1;
            round4h(v, h0, h1);
            uint32_t off = (uint32_t)((bk0 + (it << 3)) * BSP + bn4) << 1;
            *(uint32_t*)((char*)sBh + off)     = h0;
            *(uint32_t*)((char*)sBh + off + 4) = h1;
        }
        __syncthreads();

        int r16 = lane & 15, hsel = lane >> 4;
        #pragma unroll
        for (int ks = 0; ks < 2; ++ks) {
            uint32_t bh[2][4];
            #pragma unroll
            for (int j2 = 0; j2 < 2; ++j2) {
                uint32_t boff = (uint32_t)((ks * 16 + r16) * BSP +
                                           (wn << 5) + (j2 << 4) + (hsel << 3)) << 1;
                ldm_x4_trans(bh[j2][0], bh[j2][1], bh[j2][2], bh[j2][3], uBh + boff);
            }
            #pragma unroll
            for (int ii = 0; ii < 4; ++ii) {
                uint32_t aoff = (uint32_t)(((wm << 6) + (ii << 4) + r16) * SP +
                                           ks * 16 + (hsel << 3)) << 1;
                uint32_t ah0, ah1, ah2, ah3, al0, al1, al2, al3;
                ldm_x4(ah0, ah1, ah2, ah3, uAh + aoff);
                ldm_x4(al0, al1, al2, al3, uAl + aoff);
                #pragma unroll
                for (int j2 = 0; j2 < 2; ++j2) {
                    mma16816h(acc[ii][2*j2],   ah0, ah1, ah2, ah3, bh[j2][0], bh[j2][1]);
                    mma16816h(acc[ii][2*j2+1], ah0, ah1, ah2, ah3, bh[j2][2], bh[j2][3]);
                    mma16816h(acc[ii][2*j2],   al0, al1, al2, al3, bh[j2][0], bh[j2][1]);
                    mma16816h(acc[ii][2*j2+1], al0, al1, al2, al3, bh[j2][2], bh[j2][3]);
                }
            }
        }
        __syncthreads();
    }

    int g = lane >> 2, q = lane & 3;
    #pragma unroll
    for (int i = 0; i < 4; ++i) {
        #pragma unroll
        for (int half = 0; half < 2; ++half) {
            int m = m0 + (wm << 6) + (i << 4) + g + (half << 3);
            size_t base;
            if (mode == 0) {
                base = (size_t)m * N + n0;
            } else {
                int b = m >> 11, t = m & (Tt - 1), h = n0 >> 7;
                base = ((size_t)(b * H + h) * Tt + t) << 7;
            }
            #pragma unroll
            for (int j = 0; j < 4; ++j) {
                int nl = (wn << 5) + (j << 3) + (q << 1);
                float vx = acc[i][j][half * 2];
                float vy = acc[i][j][half * 2 + 1];
                if (mode == 3) {
                    *(uint32_t*)((char*)Ch + (base + nl) * 2) = pack_h(vx, vy);
                } else {
                    *(float2*)(C + base + nl) = make_float2(vx, vy);
                }
            }
        }
    }
}

// ---- fused QKV projection ----
__global__ __launch_bounds__(256, 2) void qkv_gemm_kernel(
    const float* __restrict__ A,
    const float* __restrict__ Wq, const float* __restrict__ Wk,
    const float* __restrict__ Wv,
    float* __restrict__ Qo, float* __restrict__ Ko, __half* __restrict__ Vh)
{
    int x = blockIdx.x;
    int m0 = blockIdx.y << 7;
    if (x < 16)      gemm_body(A, Wq, Qo, nullptr, NH*HD,  HIDD, 1, NH,  m0, x << 7);
    else if (x < 20) gemm_body(A, Wk, Ko, nullptr, KVH*HD, HIDD, 1, KVH, m0, (x - 16) << 7);
    else             gemm_body(A, Wv, nullptr, Vh, KVH*HD, HIDD, 3, KVH, m0, (x - 20) << 7);
}

// ---- generic GEMM (output projection) ----
__global__ __launch_bounds__(256, 2) void tc_gemm_kernel(
    const float* __restrict__ A, const float* __restrict__ W,
    float* __restrict__ C, int N, int K, int mode, int H)
{
    gemm_body(A, W, C, nullptr, N, K, mode, H, blockIdx.y << 7, blockIdx.x << 7);
}

// -------- RoPE + convert: fp32 [B,H,T,HD] -> fp16 (hi/lo or rounded) -------
__global__ void rope_cvt_kernel(const float* __restrict__ X,
                                const float* __restrict__ cs, const float* __restrict__ sn,
                                __half* __restrict__ Xh, __half* __restrict__ Xl,
                                int total)
{
    int i = blockIdx.x * blockDim.x + threadIdx.x;
    if (i >= total) return;
    int d = i & 63;
    int rest = i >> 6;
    int t = rest & (Tt - 1);
    const float* row = X + ((size_t)rest << 7);
    float x1 = row[d], x2 = row[d + 64];
    float c1 = cs[(t << 7) + d],      s1 = sn[(t << 7) + d];
    float c2 = cs[(t << 7) + d + 64], s2 = sn[(t << 7) + d + 64];
    float y1 = x1 * c1 - x2 * s1;
    float y2 = x2 * c2 + x1 * s2;
    size_t base = ((size_t)rest << 7) + d;
    __half h1 = __float2half_rn(y1);
    __half h2 = __float2half_rn(y2);
    Xh[base]      = h1;
    Xh[base + 64] = h2;
    if (Xl) {
        Xl[base]      = __float2half_rn(y1 - __half2float(h1));
        Xl[base + 64] = __float2half_rn(y2 - __half2float(h2));
    }
}

// ========== Flash attention (fp16, cp.async double-buffered KV, Q in regs) =
#define FSP   136
#define F_QH  0
#define F_QL  34816
#define F_KV  69632
#define F_STG 34816   // per stage: Kh 17408 | Vh 17408

__global__ __launch_bounds__(256, 1) void flash_mma_kernel(
    const __half* __restrict__ Qh_g, const __half* __restrict__ Ql_g,
    const __half* __restrict__ Kh_g, const __half* __restrict__ Vh_g,
    float* __restrict__ ctx)
{
    extern __shared__ char fsm[];
    const uint32_t sb = smem_u32(fsm);

    int tid = threadIdx.x, wid = tid >> 5, lane = tid & 31;
    int g = lane >> 2, qd = lane & 3;
    int r16 = lane & 15, hsel = lane >> 4;
    int qt = gridDim.x - 1 - blockIdx.x;
    int bh = blockIdx.y;
    int b = bh >> 4, h = bh & 15, kvh = h >> 2;

    size_t qoff  = ((size_t)(b * NH + h) * Tt + qt * 128) << 7;
    size_t kvoff = ((size_t)(b * KVH + kvh) * Tt) << 7;

    int ntiles = 2 * qt + 2;

    // ---- issue Q + KV0 (group 0), KV1 (group 1) ----
    #pragma unroll
    for (int r = 0; r < 8; ++r) {
        int e = tid + r * 256;
        int row = e >> 4, seg = e & 15;
        size_t go = qoff + ((size_t)row << 7) + seg * 8;
        uint32_t so = (uint32_t)(row * FSP + seg * 8) * 2;
        cpa16(sb + F_QH + so, Qh_g + go);
        cpa16(sb + F_QL + so, Ql_g + go);
    }
    #pragma unroll
    for (int r = 0; r < 4; ++r) {
        int e = tid + r * 256;
        int row = e >> 4, seg = e & 15;
        size_t go = kvoff + ((size_t)row << 7) + seg * 8;
        uint32_t so = (uint32_t)(row * FSP + seg * 8) * 2;
        cpa16(sb + F_KV + so,         Kh_g + go);
        cpa16(sb + F_KV + 17408 + so, Vh_g + go);
    }
    CPA_COMMIT();
    #pragma unroll
    for (int r = 0; r < 4; ++r) {
        int e = tid + r * 256;
        int row = e >> 4, seg = e & 15;
        size_t go = kvoff + ((size_t)(64 + row) << 7) + seg * 8;
        uint32_t so = (uint32_t)(row * FSP + seg * 8) * 2;
        cpa16(sb + F_KV + F_STG + so,         Kh_g + go);
        cpa16(sb + F_KV + F_STG + 17408 + so, Vh_g + go);
    }
    CPA_COMMIT();

    CPA_WAIT1();
    __syncthreads();

    // ---- hoist Q fragments into registers (loop-invariant) ----
    uint32_t qfh[8][4], qfl[8][4];
    #pragma unroll
    for (int ks = 0; ks < 8; ++ks) {
        uint32_t aoff = (uint32_t)((wid * 16 + r16) * FSP + ks * 16 + (hsel << 3)) << 1;
        ldm_x4(qfh[ks][0], qfh[ks][1], qfh[ks][2], qfh[ks][3], sb + F_QH + aoff);
        ldm_x4(qfl[ks][0], qfl[ks][1], qfl[ks][2], qfl[ks][3], sb + F_QL + aoff);
    }

    float o[16][4];
    #pragma unroll
    for (int i = 0; i < 16; ++i)
        #pragma unroll
        for (int e = 0; e < 4; ++e) o[i][e] = 0.f;
    float m0 = -1e30f, m1 = -1e30f, l0 = 0.f, l1 = 0.f;
    const float alpha = 0.08838834764831845f * 1.4426950408889634f;

    int qbase = qt * 128 + wid * 16;

    for (int jt = 0; jt < ntiles; ++jt) {
        uint32_t st = sb + F_KV + (jt & 1) * F_STG;
        if (jt > 0) {
            if (jt == ntiles - 1) { CPA_WAIT0(); } else { CPA_WAIT1(); }
            __syncthreads();
        }

        // ---- S = (Qh+Ql) K^T, 2 fp16 terms ----
        float s[8][4];
        #pragma unroll
        for (int t8 = 0; t8 < 8; ++t8)
            #pragma unroll
            for (int e = 0; e < 4; ++e) s[t8][e] = 0.f;

        #pragma unroll
        for (int ks = 0; ks < 8; ++ks) {
            #pragma unroll
            for (int nt = 0; nt < 4; ++nt) {
                uint32_t koff = (uint32_t)((nt * 16 + r16) * FSP + ks * 16 + (hsel << 3)) << 1;
                uint32_t kh0, kh1, kh2, kh3;
                ldm_x4(kh0, kh1, kh2, kh3, st + koff);
                mma16816h(s[2*nt],   qfh[ks][0], qfh[ks][1], qfh[ks][2], qfh[ks][3], kh0, kh2);
                mma16816h(s[2*nt+1], qfh[ks][0], qfh[ks][1], qfh[ks][2], qfh[ks][3], kh1, kh3);
                mma16816h(s[2*nt],   qfl[ks][0], qfl[ks][1], qfl[ks][2], qfl[ks][3], kh0, kh2);
                mma16816h(s[2*nt+1], qfl[ks][0], qfl[ks][1], qfl[ks][2], qfl[ks][3], kh1, kh3);
            }
        }

        // ---- scale + causal mask ----
        int kvb = jt * 64;
        int qr0 = qbase + g;
        bool needmask = (kvb + 63 > qbase);
        #pragma unroll
        for (int t8 = 0; t8 < 8; ++t8) {
            #pragma unroll
            for (int e = 0; e < 4; ++e) {
                float val = s[t8][e] * alpha;
                if (needmask) {
                    int col = kvb + t8 * 8 + qd * 2 + (e & 1);
                    int row = (e < 2) ? qr0 : qr0 + 8;
                    if (col > row) val = -1e30f;
                }
                s[t8][e] = val;
            }
        }

        // ---- online softmax (quad reductions) ----
        float tm0 = -1e30f, tm1 = -1e30f;
        #pragma unroll
        for (int t8 = 0; t8 < 8; ++t8) {
            tm0 = fmaxf(tm0, fmaxf(s[t8][0], s[t8][1]));
            tm1 = fmaxf(tm1, fmaxf(s[t8][2], s[t8][3]));
        }
        tm0 = fmaxf(tm0, __shfl_xor_sync(0xffffffffu, tm0, 1));
        tm0 = fmaxf(tm0, __shfl_xor_sync(0xffffffffu, tm0, 2));
        tm1 = fmaxf(tm1, __shfl_xor_sync(0xffffffffu, tm1, 1));
        tm1 = fmaxf(tm1, __shfl_xor_sync(0xffffffffu, tm1, 2));
        float nm0 = fmaxf(m0, tm0), nm1 = fmaxf(m1, tm1);
        float c0 = ex2(m0 - nm0), c1 = ex2(m1 - nm1);
        m0 = nm0; m1 = nm1;

        float ps0 = 0.f, ps1 = 0.f;
        #pragma unroll
        for (int t8 = 0; t8 < 8; ++t8) {
            s[t8][0] = ex2(s[t8][0] - nm0);
            s[t8][1] = ex2(s[t8][1] - nm0);
            s[t8][2] = ex2(s[t8][2] - nm1);
            s[t8][3] = ex2(s[t8][3] - nm1);
            ps0 += s[t8][0] + s[t8][1];
            ps1 += s[t8][2] + s[t8][3];
        }
        ps0 += __shfl_xor_sync(0xffffffffu, ps0, 1);
        ps0 += __shfl_xor_sync(0xffffffffu, ps0, 2);
        ps1 += __shfl_xor_sync(0xffffffffu, ps1, 1);
        ps1 += __shfl_xor_sync(0xffffffffu, ps1, 2);
        l0 = l0 * c0 + ps0;
        l1 = l1 * c1 + ps1;

        #pragma unroll
        for (int dt = 0; dt < 16; ++dt) {
            o[dt][0] *= c0; o[dt][1] *= c0;
            o[dt][2] *= c1; o[dt][3] *= c1;
        }

        // ---- O += P V (1 fp16 term) ----
        #pragma unroll
        for (int j = 0; j < 4; ++j) {
            uint32_t ph0 = pack_h(s[2*j][0],   s[2*j][1]);
            uint32_t ph1 = pack_h(s[2*j][2],   s[2*j][3]);
            uint32_t ph2 = pack_h(s[2*j+1][0], s[2*j+1][1]);
            uint32_t ph3 = pack_h(s[2*j+1][2], s[2*j+1][3]);
            #pragma unroll
            for (int dt = 0; dt < 8; ++dt) {
                uint32_t voff = (uint32_t)((j * 16 + r16) * FSP + dt * 16 + (hsel << 3)) << 1;
                uint32_t vh0, vh1, vh2, vh3;
                ldm_x4_trans(vh0, vh1, vh2, vh3, st + 17408 + voff);
                mma16816h(o[2*dt],   ph0, ph1, ph2, ph3, vh0, vh1);
                mma16816h(o[2*dt+1], ph0, ph1, ph2, ph3, vh2, vh3);
            }
        }

        __syncthreads();
        if (jt + 2 < ntiles) {
            uint32_t dst = sb + F_KV + (jt & 1) * F_STG;
            #pragma unroll
            for (int r = 0; r < 4; ++r) {
                int e = tid + r * 256;
                int row = e >> 4, seg = e & 15;
                size_t go = kvoff + ((size_t)((jt + 2) * 64 + row) << 7) + seg * 8;
                uint32_t so = (uint32_t)(row * FSP + seg * 8) * 2;
                cpa16(dst + so,         Kh_g + go);
                cpa16(dst + 17408 + so, Vh_g + go);
            }
            CPA_COMMIT();
        }
    }

    // ---- finalize ----
    float li0 = 1.f / l0, li1 = 1.f / l1;
    int t0 = qbase + g;
    float* dst0 = ctx + (size_t)(b * Tt + t0) * HIDD + h * HD;
    float* dst1 = ctx + (size_t)(b * Tt + t0 + 8) * HIDD + h * HD;
    #pragma unroll
    for (int dt = 0; dt < 16; ++dt) {
        int col = dt * 8 + qd * 2;
        float2 w0 = make_float2(o[dt][0] * li0, o[dt][1] * li0);
        float2 w1 = make_float2(o[dt][2] * li1, o[dt][3] * li1);
        *(float2*)(dst0 + col) = w0;
        *(float2*)(dst1 + col) = w1;
    }
}

// ---------------- launch ----------------
extern "C" void kernel_launch(void* const* d_in, const int* in_sizes, int n_in,
                              void* d_out, int out_size)
{
    const float* hs   = (const float*)d_in[0];
    const float* cosp = (const float*)d_in[2];
    const float* sinp = (const float*)d_in[3];
    const float* Wq   = (const float*)d_in[4];
    const float* Wk   = (const float*)d_in[5];
    const float* Wv   = (const float*)d_in[6];
    const float* Wo   = (const float*)d_in[7];
    float* out = (float*)d_out;

    float *pQ, *pK, *pC;
    __half *pQh, *pQl, *pKh, *pVh;
    cudaGetSymbolAddress((void**)&pQ,  g_Q);
    cudaGetSymbolAddress((void**)&pK,  g_K);
    cudaGetSymbolAddress((void**)&pQh, g_Qh);
    cudaGetSymbolAddress((void**)&pQl, g_Ql);
    cudaGetSymbolAddress((void**)&pKh, g_Kh);
    cudaGetSymbolAddress((void**)&pVh, g_Vh);
    cudaGetSymbolAddress((void**)&pC,  g_ctx);

    // Fused QKV projection (fp16 2-term); V epilogue writes fp16 directly
    qkv_gemm_kernel<<<dim3(24, 32), 256>>>(hs, Wq, Wk, Wv, pQ, pK, pVh);

    // RoPE + convert: Q -> fp16 hi/lo, K -> fp16 rounded
    int totQ = Bb * NH  * Tt * 64;
    int totK = Bb * KVH * Tt * 64;
    rope_cvt_kernel<<<totQ / 256, 256>>>(pQ, cosp, sinp, pQh, pQl, totQ);
    rope_cvt_kernel<<<totK / 256, 256>>>(pK, cosp, sinp, pKh, nullptr, totK);

    // Flash attention (cp.async double-buffered KV, Q fragments in registers)
    size_t fsh = (size_t)F_KV + 2 * F_STG;   // 139264
    cudaFuncSetAttribute(flash_mma_kernel, cudaFuncAttributeMaxDynamicSharedMemorySize, (int)fsh);
    flash_mma_kernel<<<dim3(Tt/128, Bb*NH), 256, fsh>>>(pQh, pQl, pKh, pVh, pC);

    // Output projection (fp16 2-term) -> d_out
    tc_gemm_kernel<<<dim3(16, 32), 256>>>(pC, Wo, out, HIDD, HIDD, 0, 0);
}

// round 17
// speedup vs baseline: 1.4961x; 1.0874x over previous
#include <cuda_runtime.h>
#include <cuda_bf16.h>
#include <cuda_fp16.h>
#include <cstdint>
#include <math.h>

#define Bb   2
#define Tt   2048
#define HIDD 2048
#define NH   16
#define KVH  4
#define HD   128
#define Mrows (Bb*Tt)

// ---------------- scratch (device globals: allocation-free) ----------------
__device__ float g_Q[(size_t)Bb*NH*Tt*HD];        // fp32 Q (pre-RoPE)
__device__ float g_K[(size_t)Bb*KVH*Tt*HD];       // fp32 K (pre-RoPE)
__device__ __half g_hsh[(size_t)Mrows*HIDD];      // hs hi
__device__ __half g_hsl[(size_t)Mrows*HIDD];      // hs lo
__device__ __half g_wqh[(size_t)HIDD*NH*HD];      // weights, fp16 rounded
__device__ __half g_wkh[(size_t)HIDD*KVH*HD];
__device__ __half g_wvh[(size_t)HIDD*KVH*HD];
__device__ __half g_woh[(size_t)HIDD*HIDD];
__device__ __half g_Qh[(size_t)Bb*NH*Tt*HD];      // fp16 Q hi (post-RoPE)
__device__ __half g_Ql[(size_t)Bb*NH*Tt*HD];      // fp16 Q lo
__device__ __half g_Kh[(size_t)Bb*KVH*Tt*HD];     // fp16 K (rounded, post-RoPE)
__device__ __half g_Vh[(size_t)Bb*KVH*Tt*HD];     // fp16 V (rounded)
__device__ __half g_cth[(size_t)Mrows*HIDD];      // ctx hi
__device__ __half g_ctl[(size_t)Mrows*HIDD];      // ctx lo

// ================= mma.sync helpers (compute_103-safe) =====================
__device__ __forceinline__ uint32_t smem_u32(const void* p) {
    uint32_t a;
    asm("{ .reg .u64 t; cvta.to.shared.u64 t, %1; cvt.u32.u64 %0, t; }" : "=r"(a) : "l"(p));
    return a;
}
__device__ __forceinline__ void ldm_x4(uint32_t& r0, uint32_t& r1, uint32_t& r2,
                                       uint32_t& r3, uint32_t addr) {
    asm volatile("ldmatrix.sync.aligned.m8n8.x4.shared.b16 {%0,%1,%2,%3}, [%4];"
                 : "=r"(r0), "=r"(r1), "=r"(r2), "=r"(r3) : "r"(addr));
}
__device__ __forceinline__ void ldm_x4_trans(uint32_t& r0, uint32_t& r1, uint32_t& r2,
                                             uint32_t& r3, uint32_t addr) {
    asm volatile("ldmatrix.sync.aligned.m8n8.x4.trans.shared.b16 {%0,%1,%2,%3}, [%4];"
                 : "=r"(r0), "=r"(r1), "=r"(r2), "=r"(r3) : "r"(addr));
}
__device__ __forceinline__ void mma16816h(float* c, uint32_t a0, uint32_t a1,
                                          uint32_t a2, uint32_t a3,
                                          uint32_t b0, uint32_t b1) {
    asm volatile(
        "mma.sync.aligned.m16n8k16.row.col.f32.f16.f16.f32 "
        "{%0,%1,%2,%3}, {%4,%5,%6,%7}, {%8,%9}, {%0,%1,%2,%3};"
        : "+f"(c[0]), "+f"(c[1]), "+f"(c[2]), "+f"(c[3])
        : "r"(a0), "r"(a1), "r"(a2), "r"(a3), "r"(b0), "r"(b1));
}
__device__ __forceinline__ float ex2(float x) {
    float r;
    asm("ex2.approx.f32 %0, %1;" : "=f"(r) : "f"(x));
    return r;
}
__device__ __forceinline__ void cpa16(uint32_t dst, const void* src) {
    asm volatile("cp.async.cg.shared.global [%0], [%1], 16;" :: "r"(dst), "l"(src));
}
#define CPA_COMMIT() asm volatile("cp.async.commit_group;" ::: "memory")
#define CPA_WAIT1()  asm volatile("cp.async.wait_group 1;" ::: "memory")
#define CPA_WAIT0()  asm volatile("cp.async.wait_group 0;" ::: "memory")

// ---- fp16 split helpers ----
__device__ __forceinline__ void split4h(float4 v, uint32_t& h0, uint32_t& h1,
                                        uint32_t& l0, uint32_t& l1) {
    __half2 a = __floats2half2_rn(v.x, v.y);
    __half2 b = __floats2half2_rn(v.z, v.w);
    __half2 ra = __floats2half2_rn(v.x - __half2float(a.x),
                                   v.y - __half2float(a.y));
    __half2 rb = __floats2half2_rn(v.z - __half2float(b.x),
                                   v.w - __half2float(b.y));
    h0 = *(uint32_t*)&a; h1 = *(uint32_t*)&b;
    l0 = *(uint32_t*)&ra; l1 = *(uint32_t*)&rb;
}
__device__ __forceinline__ void round4h(float4 v, uint32_t& h0, uint32_t& h1) {
    __half2 a = __floats2half2_rn(v.x, v.y);
    __half2 b = __floats2half2_rn(v.z, v.w);
    h0 = *(uint32_t*)&a; h1 = *(uint32_t*)&b;
}
__device__ __forceinline__ uint32_t pack_h(float x, float y) {
    __half2 h = __floats2half2_rn(x, y);
    return *(uint32_t*)&h;
}
__device__ __forceinline__ uint32_t pack_hl(float x, float y, uint32_t hbits) {
    __half2 h = *(__half2*)&hbits;
    __half2 l = __floats2half2_rn(x - __half2float(h.x), y - __half2float(h.y));
    return *(uint32_t*)&l;
}

// ---------------- convert kernels (fp32 -> fp16) ----------------
__global__ void cvt_split_kernel(const float* __restrict__ x,
                                 __half* __restrict__ h, __half* __restrict__ l, int n4)
{
    int i = blockIdx.x * blockDim.x + threadIdx.x;
    if (i >= n4) return;
    float4 v = *(const float4*)(x + (size_t)i * 4);
    uint32_t h0, h1, l0, l1;
    split4h(v, h0, h1, l0, l1);
    *(uint32_t*)((char*)h + (size_t)i * 8)     = h0;
    *(uint32_t*)((char*)h + (size_t)i * 8 + 4) = h1;
    *(uint32_t*)((char*)l + (size_t)i * 8)     = l0;
    *(uint32_t*)((char*)l + (size_t)i * 8 + 4) = l1;
}
__global__ void cvt_round_kernel(const float* __restrict__ x,
                                 __half* __restrict__ h, int n4)
{
    int i = blockIdx.x * blockDim.x + threadIdx.x;
    if (i >= n4) return;
    float4 v = *(const float4*)(x + (size_t)i * 4);
    uint32_t h0, h1;
    round4h(v, h0, h1);
    *(uint32_t*)((char*)h + (size_t)i * 8)     = h0;
    *(uint32_t*)((char*)h + (size_t)i * 8 + 4) = h1;
}

// ======== fp16 2-term GEMM, cp.async double-buffered, 2 CTAs/SM ============
// A (hi/lo fp16) [M,K], B (fp16) [K,N]; BK=32.
// mode 0: fp32 row-major.  mode 1: fp32 head layout.  mode 3: fp16 head.
#define SP  40
#define BSP 136
#define GA_H 0
#define GA_L 10240
#define GB_H 20480
#define G_STG 29184
#define G_SMEM (2 * G_STG)   // 58368

__device__ __forceinline__ void gemm_issue(
    const __half* __restrict__ Ah, const __half* __restrict__ Al,
    const __half* __restrict__ Bh,
    uint32_t st, int tid, int m0, int n0, int K, int N, int k0)
{
    #pragma unroll
    for (int r = 0; r < 2; ++r) {
        int e = tid + (r << 8);            // A: 128 rows x 4 segs (16B)
        int row = e >> 2, seg = e & 3;
        size_t go = (size_t)(m0 + row) * K + k0 + (seg << 3);
        uint32_t so = (uint32_t)(row * SP + (seg << 3)) << 1;
        cpa16(st + GA_H + so, Ah + go);
        cpa16(st + GA_L + so, Al + go);
    }
    #pragma unroll
    for (int r = 0; r < 2; ++r) {
        int e = tid + (r << 8);            // B: 32 rows x 16 segs (16B)
        int row = e >> 4, seg = e & 15;
        size_t go = (size_t)(k0 + row) * N + n0 + (seg << 3);
        uint32_t so = (uint32_t)(row * BSP + (seg << 3)) << 1;
        cpa16(st + GB_H + so, Bh + go);
    }
}

__device__ __forceinline__ void gemm_body(
    const __half* __restrict__ Ah, const __half* __restrict__ Al,
    const __half* __restrict__ Bh,
    float* __restrict__ C, __half* __restrict__ Ch,
    int N, int K, int mode, int H, int m0, int n0)
{
    extern __shared__ char gsm[];
    const uint32_t sb = smem_u32(gsm);

    int tid = threadIdx.x;
    int wid = tid >> 5, lane = tid & 31;
    int wm = wid >> 2, wn = wid & 3;
    int r16 = lane & 15, hsel = lane >> 4;

    float acc[4][4][4];
    #pragma unroll
    for (int i = 0; i < 4; ++i)
        #pragma unroll
        for (int j = 0; j < 4; ++j)
            #pragma unroll
            for (int e = 0; e < 4; ++e) acc[i][j][e] = 0.f;

    int chunks = K >> 5;
    gemm_issue(Ah, Al, Bh, sb,          tid, m0, n0, K, N, 0);
    CPA_COMMIT();
    gemm_issue(Ah, Al, Bh, sb + G_STG,  tid, m0, n0, K, N, 32);
    CPA_COMMIT();

    for (int i = 0; i < chunks; ++i) {
        uint32_t st = sb + (i & 1) * G_STG;
        if (i == chunks - 1) { CPA_WAIT0(); } else { CPA_WAIT1(); }
        __syncthreads();

        #pragma unroll
        for (int ks = 0; ks < 2; ++ks) {
            uint32_t bh[2][4];
            #pragma unroll
            for (int j2 = 0; j2 < 2; ++j2) {
                uint32_t boff = (uint32_t)((ks * 16 + r16) * BSP +
                                           (wn << 5) + (j2 << 4) + (hsel << 3)) << 1;
                ldm_x4_trans(bh[j2][0], bh[j2][1], bh[j2][2], bh[j2][3], st + GB_H + boff);
            }
            #pragma unroll
            for (int ii = 0; ii < 4; ++ii) {
                uint32_t aoff = (uint32_t)(((wm << 6) + (ii << 4) + r16) * SP +
                                           ks * 16 + (hsel << 3)) << 1;
                uint32_t ah0, ah1, ah2, ah3, al0, al1, al2, al3;
                ldm_x4(ah0, ah1, ah2, ah3, st + GA_H + aoff);
                ldm_x4(al0, al1, al2, al3, st + GA_L + aoff);
                #pragma unroll
                for (int j2 = 0; j2 < 2; ++j2) {
                    mma16816h(acc[ii][2*j2],   ah0, ah1, ah2, ah3, bh[j2][0], bh[j2][1]);
                    mma16816h(acc[ii][2*j2+1], ah0, ah1, ah2, ah3, bh[j2][2], bh[j2][3]);
                    mma16816h(acc[ii][2*j2],   al0, al1, al2, al3, bh[j2][0], bh[j2][1]);
                    mma16816h(acc[ii][2*j2+1], al0, al1, al2, al3, bh[j2][2], bh[j2][3]);
                }
            }
        }
        __syncthreads();
        if (i + 2 < chunks) {
            gemm_issue(Ah, Al, Bh, sb + (i & 1) * G_STG, tid, m0, n0, K, N, (i + 2) << 5);
            CPA_COMMIT();
        }
    }

    int g = lane >> 2, q = lane & 3;
    #pragma unroll
    for (int i = 0; i < 4; ++i) {
        #pragma unroll
        for (int half = 0; half < 2; ++half) {
            int m = m0 + (wm << 6) + (i << 4) + g + (half << 3);
            size_t base;
            if (mode == 0) {
                base = (size_t)m * N + n0;
            } else {
                int b = m >> 11, t = m & (Tt - 1), h = n0 >> 7;
                base = ((size_t)(b * H + h) * Tt + t) << 7;
            }
            #pragma unroll
            for (int j = 0; j < 4; ++j) {
                int nl = (wn << 5) + (j << 3) + (q << 1);
                float vx = acc[i][j][half * 2];
                float vy = acc[i][j][half * 2 + 1];
                if (mode == 3) {
                    *(uint32_t*)((char*)Ch + (base + nl) * 2) = pack_h(vx, vy);
                } else {
                    *(float2*)(C + base + nl) = make_float2(vx, vy);
                }
            }
        }
    }
}

// ---- fused QKV projection ----
__global__ __launch_bounds__(256, 2) void qkv_gemm_kernel(
    const __half* __restrict__ Ah, const __half* __restrict__ Al,
    const __half* __restrict__ Wq, const __half* __restrict__ Wk,
    const __half* __restrict__ Wv,
    float* __restrict__ Qo, float* __restrict__ Ko, __half* __restrict__ Vh)
{
    int x = blockIdx.x;
    int m0 = blockIdx.y << 7;
    if (x < 16)      gemm_body(Ah, Al, Wq, Qo, nullptr, NH*HD,  HIDD, 1, NH,  m0, x << 7);
    else if (x < 20) gemm_body(Ah, Al, Wk, Ko, nullptr, KVH*HD, HIDD, 1, KVH, m0, (x - 16) << 7);
    else             gemm_body(Ah, Al, Wv, nullptr, Vh, KVH*HD, HIDD, 3, KVH, m0, (x - 20) << 7);
}

// ---- output projection ----
__global__ __launch_bounds__(256, 2) void tc_gemm_kernel(
    const __half* __restrict__ Ah, const __half* __restrict__ Al,
    const __half* __restrict__ W, float* __restrict__ C, int N, int K)
{
    gemm_body(Ah, Al, W, C, nullptr, N, K, 0, 0, blockIdx.y << 7, blockIdx.x << 7);
}

// -------- RoPE + convert: fp32 [B,H,T,HD] -> fp16 (hi/lo or rounded) -------
__global__ void rope_cvt_kernel(const float* __restrict__ X,
                                const float* __restrict__ cs, const float* __restrict__ sn,
                                __half* __restrict__ Xh, __half* __restrict__ Xl,
                                int total)
{
    int i = blockIdx.x * blockDim.x + threadIdx.x;
    if (i >= total) return;
    int d = i & 63;
    int rest = i >> 6;
    int t = rest & (Tt - 1);
    const float* row = X + ((size_t)rest << 7);
    float x1 = row[d], x2 = row[d + 64];
    float c1 = cs[(t << 7) + d],      s1 = sn[(t << 7) + d];
    float c2 = cs[(t << 7) + d + 64], s2 = sn[(t << 7) + d + 64];
    float y1 = x1 * c1 - x2 * s1;
    float y2 = x2 * c2 + x1 * s2;
    size_t base = ((size_t)rest << 7) + d;
    __half h1 = __float2half_rn(y1);
    __half h2 = __float2half_rn(y2);
    Xh[base]      = h1;
    Xh[base + 64] = h2;
    if (Xl) {
        Xl[base]      = __float2half_rn(y1 - __half2float(h1));
        Xl[base + 64] = __float2half_rn(y2 - __half2float(h2));
    }
}

// ========== Flash attention (fp16, cp.async double-buffered KV, Q in regs) =
#define FSP   136
#define F_QH  0
#define F_QL  34816
#define F_KV  69632
#define F_STG 34816   // per stage: Kh 17408 | Vh 17408

__global__ __launch_bounds__(256, 1) void flash_mma_kernel(
    const __half* __restrict__ Qh_g, const __half* __restrict__ Ql_g,
    const __half* __restrict__ Kh_g, const __half* __restrict__ Vh_g,
    __half* __restrict__ Ch, __half* __restrict__ Cl)
{
    extern __shared__ char fsm[];
    const uint32_t sb = smem_u32(fsm);

    int tid = threadIdx.x, wid = tid >> 5, lane = tid & 31;
    int g = lane >> 2, qd = lane & 3;
    int r16 = lane & 15, hsel = lane >> 4;
    int qt = gridDim.x - 1 - blockIdx.x;
    int bh = blockIdx.y;
    int b = bh >> 4, h = bh & 15, kvh = h >> 2;

    size_t qoff  = ((size_t)(b * NH + h) * Tt + qt * 128) << 7;
    size_t kvoff = ((size_t)(b * KVH + kvh) * Tt) << 7;

    int ntiles = 2 * qt + 2;

    #pragma unroll
    for (int r = 0; r < 8; ++r) {
        int e = tid + r * 256;
        int row = e >> 4, seg = e & 15;
        size_t go = qoff + ((size_t)row << 7) + seg * 8;
        uint32_t so = (uint32_t)(row * FSP + seg * 8) * 2;
        cpa16(sb + F_QH + so, Qh_g + go);
        cpa16(sb + F_QL + so, Ql_g + go);
    }
    #pragma unroll
    for (int r = 0; r < 4; ++r) {
        int e = tid + r * 256;
        int row = e >> 4, seg = e & 15;
        size_t go = kvoff + ((size_t)row << 7) + seg * 8;
        uint32_t so = (uint32_t)(row * FSP + seg * 8) * 2;
        cpa16(sb + F_KV + so,         Kh_g + go);
        cpa16(sb + F_KV + 17408 + so, Vh_g + go);
    }
    CPA_COMMIT();
    #pragma unroll
    for (int r = 0; r < 4; ++r) {
        int e = tid + r * 256;
        int row = e >> 4, seg = e & 15;
        size_t go = kvoff + ((size_t)(64 + row) << 7) + seg * 8;
        uint32_t so = (uint32_t)(row * FSP + seg * 8) * 2;
        cpa16(sb + F_KV + F_STG + so,         Kh_g + go);
        cpa16(sb + F_KV + F_STG + 17408 + so, Vh_g + go);
    }
    CPA_COMMIT();

    CPA_WAIT1();
    __syncthreads();

    uint32_t qfh[8][4], qfl[8][4];
    #pragma unroll
    for (int ks = 0; ks < 8; ++ks) {
        uint32_t aoff = (uint32_t)((wid * 16 + r16) * FSP + ks * 16 + (hsel << 3)) << 1;
        ldm_x4(qfh[ks][0], qfh[ks][1], qfh[ks][2], qfh[ks][3], sb + F_QH + aoff);
        ldm_x4(qfl[ks][0], qfl[ks][1], qfl[ks][2], qfl[ks][3], sb + F_QL + aoff);
    }

    float o[16][4];
    #pragma unroll
    for (int i = 0; i < 16; ++i)
        #pragma unroll
        for (int e = 0; e < 4; ++e) o[i][e] = 0.f;
    float m0 = -1e30f, m1 = -1e30f, l0 = 0.f, l1 = 0.f;
    const float alpha = 0.08838834764831845f * 1.4426950408889634f;

    int qbase = qt * 128 + wid * 16;

    for (int jt = 0; jt < ntiles; ++jt) {
        uint32_t st = sb + F_KV + (jt & 1) * F_STG;
        if (jt > 0) {
            if (jt == ntiles - 1) { CPA_WAIT0(); } else { CPA_WAIT1(); }
            __syncthreads();
        }

        float s[8][4];
        #pragma unroll
        for (int t8 = 0; t8 < 8; ++t8)
            #pragma unroll
            for (int e = 0; e < 4; ++e) s[t8][e] = 0.f;

        #pragma unroll
        for (int ks = 0; ks < 8; ++ks) {
            #pragma unroll
            for (int nt = 0; nt < 4; ++nt) {
                uint32_t koff = (uint32_t)((nt * 16 + r16) * FSP + ks * 16 + (hsel << 3)) << 1;
                uint32_t kh0, kh1, kh2, kh3;
                ldm_x4(kh0, kh1, kh2, kh3, st + koff);
                mma16816h(s[2*nt],   qfh[ks][0], qfh[ks][1], qfh[ks][2], qfh[ks][3], kh0, kh2);
                mma16816h(s[2*nt+1], qfh[ks][0], qfh[ks][1], qfh[ks][2], qfh[ks][3], kh1, kh3);
                mma16816h(s[2*nt],   qfl[ks][0], qfl[ks][1], qfl[ks][2], qfl[ks][3], kh0, kh2);
                mma16816h(s[2*nt+1], qfl[ks][0], qfl[ks][1], qfl[ks][2], qfl[ks][3], kh1, kh3);
            }
        }

        int kvb = jt * 64;
        int qr0 = qbase + g;
        bool needmask = (kvb + 63 > qbase);
        #pragma unroll
        for (int t8 = 0; t8 < 8; ++t8) {
            #pragma unroll
            for (int e = 0; e < 4; ++e) {
                float val = s[t8][e] * alpha;
                if (needmask) {
                    int col = kvb + t8 * 8 + qd * 2 + (e & 1);
                    int row = (e < 2) ? qr0 : qr0 + 8;
                    if (col > row) val = -1e30f;
                }
                s[t8][e] = val;
            }
        }

        float tm0 = -1e30f, tm1 = -1e30f;
        #pragma unroll
        for (int t8 = 0; t8 < 8; ++t8) {
            tm0 = fmaxf(tm0, fmaxf(s[t8][0], s[t8][1]));
            tm1 = fmaxf(tm1, fmaxf(s[t8][2], s[t8][3]));
        }
        tm0 = fmaxf(tm0, __shfl_xor_sync(0xffffffffu, tm0, 1));
        tm0 = fmaxf(tm0, __shfl_xor_sync(0xffffffffu, tm0, 2));
        tm1 = fmaxf(tm1, __shfl_xor_sync(0xffffffffu, tm1, 1));
        tm1 = fmaxf(tm1, __shfl_xor_sync(0xffffffffu, tm1, 2));
        float nm0 = fmaxf(m0, tm0), nm1 = fmaxf(m1, tm1);
        float c0 = ex2(m0 - nm0), c1 = ex2(m1 - nm1);
        m0 = nm0; m1 = nm1;

        float ps0 = 0.f, ps1 = 0.f;
        #pragma unroll
        for (int t8 = 0; t8 < 8; ++t8) {
            s[t8][0] = ex2(s[t8][0] - nm0);
            s[t8][1] = ex2(s[t8][1] - nm0);
            s[t8][2] = ex2(s[t8][2] - nm1);
            s[t8][3] = ex2(s[t8][3] - nm1);
            ps0 += s[t8][0] + s[t8][1];
            ps1 += s[t8][2] + s[t8][3];
        }
        ps0 += __shfl_xor_sync(0xffffffffu, ps0, 1);
        ps0 += __shfl_xor_sync(0xffffffffu, ps0, 2);
        ps1 += __shfl_xor_sync(0xffffffffu, ps1, 1);
        ps1 += __shfl_xor_sync(0xffffffffu, ps1, 2);
        l0 = l0 * c0 + ps0;
        l1 = l1 * c1 + ps1;

        #pragma unroll
        for (int dt = 0; dt < 16; ++dt) {
            o[dt][0] *= c0; o[dt][1] *= c0;
            o[dt][2] *= c1; o[dt][3] *= c1;
        }

        #pragma unroll
        for (int j = 0; j < 4; ++j) {
            uint32_t ph0 = pack_h(s[2*j][0],   s[2*j][1]);
            uint32_t ph1 = pack_h(s[2*j][2],   s[2*j][3]);
            uint32_t ph2 = pack_h(s[2*j+1][0], s[2*j+1][1]);
            uint32_t ph3 = pack_h(s[2*j+1][2], s[2*j+1][3]);
            #pragma unroll
            for (int dt = 0; dt < 8; ++dt) {
                uint32_t voff = (uint32_t)((j * 16 + r16) * FSP + dt * 16 + (hsel << 3)) << 1;
                uint32_t vh0, vh1, vh2, vh3;
                ldm_x4_trans(vh0, vh1, vh2, vh3, st + 17408 + voff);
                mma16816h(o[2*dt],   ph0, ph1, ph2, ph3, vh0, vh1);
                mma16816h(o[2*dt+1], ph0, ph1, ph2, ph3, vh2, vh3);
            }
        }

        __syncthreads();
        if (jt + 2 < ntiles) {
            uint32_t dst = sb + F_KV + (jt & 1) * F_STG;
            #pragma unroll
            for (int r = 0; r < 4; ++r) {
                int e = tid + r * 256;
                int row = e >> 4, seg = e & 15;
                size_t go = kvoff + ((size_t)((jt + 2) * 64 + row) << 7) + seg * 8;
                uint32_t so = (uint32_t)(row * FSP + seg * 8) * 2;
                cpa16(dst + so,         Kh_g + go);
                cpa16(dst + 17408 + so, Vh_g + go);
            }
            CPA_COMMIT();
        }
    }

    // ---- finalize: write ctx as fp16 hi/lo (exact split of fp32 value) ----
    float li0 = 1.f / l0, li1 = 1.f / l1;
    int t0 = qbase + g;
    size_t d0 = (size_t)(b * Tt + t0) * HIDD + h * HD;
    size_t d1 = (size_t)(b * Tt + t0 + 8) * HIDD + h * HD;
    #pragma unroll
    for (int dt = 0; dt < 16; ++dt) {
        int col = dt * 8 + qd * 2;
        float x0 = o[dt][0] * li0, y0 = o[dt][1] * li0;
        float x1 = o[dt][2] * li1, y1 = o[dt][3] * li1;
        uint32_t hp0 = pack_h(x0, y0), lp0 = pack_hl(x0, y0, hp0);
        uint32_t hp1 = pack_h(x1, y1), lp1 = pack_hl(x1, y1, hp1);
        *(uint32_t*)((char*)Ch + (d0 + col) * 2) = hp0;
        *(uint32_t*)((char*)Cl + (d0 + col) * 2) = lp0;
        *(uint32_t*)((char*)Ch + (d1 + col) * 2) = hp1;
        *(uint32_t*)((char*)Cl + (d1 + col) * 2) = lp1;
    }
}

// ---------------- launch ----------------
extern "C" void kernel_launch(void* const* d_in, const int* in_sizes, int n_in,
                              void* d_out, int out_size)
{
    const float* hs   = (const float*)d_in[0];
    const float* cosp = (const float*)d_in[2];
    const float* sinp = (const float*)d_in[3];
    const float* Wq   = (const float*)d_in[4];
    const float* Wk   = (const float*)d_in[5];
    const float* Wv   = (const float*)d_in[6];
    const float* Wo   = (const float*)d_in[7];
    float* out = (float*)d_out;

    float *pQ, *pK;
    __half *hsh, *hsl, *wqh, *wkh, *wvh, *woh;
    __half *pQh, *pQl, *pKh, *pVh, *cth, *ctl;
    cudaGetSymbolAddress((void**)&pQ,  g_Q);
    cudaGetSymbolAddress((void**)&pK,  g_K);
    cudaGetSymbolAddress((void**)&hsh, g_hsh); cudaGetSymbolAddress((void**)&hsl, g_hsl);
    cudaGetSymbolAddress((void**)&wqh, g_wqh); cudaGetSymbolAddress((void**)&wkh, g_wkh);
    cudaGetSymbolAddress((void**)&wvh, g_wvh); cudaGetSymbolAddress((void**)&woh, g_woh);
    cudaGetSymbolAddress((void**)&pQh, g_Qh);  cudaGetSymbolAddress((void**)&pQl, g_Ql);
    cudaGetSymbolAddress((void**)&pKh, g_Kh);  cudaGetSymbolAddress((void**)&pVh, g_Vh);
    cudaGetSymbolAddress((void**)&cth, g_cth); cudaGetSymbolAddress((void**)&ctl, g_ctl);

    // ---- pre-convert: hs -> fp16 hi/lo, weights -> fp16 rounded ----
    cvt_split_kernel<<<Mrows*HIDD/4/256, 256>>>(hs, hsh, hsl, Mrows*HIDD/4);
    cvt_round_kernel<<<HIDD*NH*HD/4/256, 256>>>(Wq, wqh, HIDD*NH*HD/4);
    cvt_round_kernel<<<HIDD*KVH*HD/4/256, 256>>>(Wk, wkh, HIDD*KVH*HD/4);
    cvt_round_kernel<<<HIDD*KVH*HD/4/256, 256>>>(Wv, wvh, HIDD*KVH*HD/4);
    cvt_round_kernel<<<HIDD*HIDD/4/256, 256>>>(Wo, woh, HIDD*HIDD/4);

    cudaFuncSetAttribute(qkv_gemm_kernel, cudaFuncAttributeMaxDynamicSharedMemorySize, G_SMEM);
    cudaFuncSetAttribute(tc_gemm_kernel,  cudaFuncAttributeMaxDynamicSharedMemorySize, G_SMEM);

    // Fused QKV projection (fp16 2-term, cp.async pipelined)
    qkv_gemm_kernel<<<dim3(24, 32), 256, G_SMEM>>>(hsh, hsl, wqh, wkh, wvh, pQ, pK, pVh);

    // RoPE + convert: Q -> fp16 hi/lo, K -> fp16 rounded
    int totQ = Bb * NH  * Tt * 64;
    int totK = Bb * KVH * Tt * 64;
    rope_cvt_kernel<<<totQ / 256, 256>>>(pQ, cosp, sinp, pQh, pQl, totQ);
    rope_cvt_kernel<<<totK / 256, 256>>>(pK, cosp, sinp, pKh, nullptr, totK);

    // Flash attention (cp.async double-buffered KV, Q fragments in registers)
    size_t fsh = (size_t)F_KV + 2 * F_STG;   // 139264
    cudaFuncSetAttribute(flash_mma_kernel, cudaFuncAttributeMaxDynamicSharedMemorySize, (int)fsh);
    flash_mma_kernel<<<dim3(Tt/128, Bb*NH), 256, fsh>>>(pQh, pQl, pKh, pVh, cth, ctl);

    // Output projection (fp16 2-term, cp.async pipelined) -> d_out
    tc_gemm_kernel<<<dim3(16, 32), 256, G_SMEM>>>(cth, ctl, woh, out, HIDD, HIDD);
}